// round 8
// baseline (speedup 1.0000x reference)
#include <cuda_runtime.h>
#include <cuda_fp16.h>
#include <cstdint>

// ---------------------------------------------------------------------------
// Problem constants
// ---------------------------------------------------------------------------
#define BATCH   2048
#define NTOK    49
#define HEADS   16
#define HDIM    32
#define CDIM    512
#define MW      64
#define MTOT    (BATCH*NTOK)   // 100352
#define QKVCOLS (3*CDIM)       // 1536

__device__ float g_qkv[(size_t)MTOT * QKVCOLS];
__device__ __half g_ah[(size_t)MTOT * CDIM];     // hidden fp16
__device__ __half g_wh[(size_t)QKVCOLS * CDIM];  // weights fp16 (q|k|v rows)

// ---------------------------------------------------------------------------
// helpers
// ---------------------------------------------------------------------------
__device__ __forceinline__ uint32_t smem_u32(const void* p) {
    uint32_t a;
    asm("{ .reg .u64 t; cvta.to.shared.u64 t, %1; cvt.u32.u64 %0, t; }" : "=r"(a) : "l"(p));
    return a;
}
__device__ __forceinline__ void cp16(uint32_t saddr, const void* gaddr) {
    asm volatile("cp.async.cg.shared.global [%0], [%1], 16;" :: "r"(saddr), "l"(gaddr) : "memory");
}
__device__ __forceinline__ void cp_commit() {
    asm volatile("cp.async.commit_group;" ::: "memory");
}
template<int N> __device__ __forceinline__ void cp_wait() {
    asm volatile("cp.async.wait_group %0;" :: "n"(N) : "memory");
}
#define LDX4(d, addr) \
    asm volatile("ldmatrix.sync.aligned.m8n8.x4.shared.b16 {%0,%1,%2,%3}, [%4];" \
        : "=r"((d)[0]), "=r"((d)[1]), "=r"((d)[2]), "=r"((d)[3]) : "r"(addr))

__device__ __forceinline__ void mma_f16(float* c, const uint32_t* a, uint32_t b0, uint32_t b1) {
    asm volatile(
        "mma.sync.aligned.m16n8k16.row.col.f32.f16.f16.f32 "
        "{%0,%1,%2,%3}, {%4,%5,%6,%7}, {%8,%9}, {%0,%1,%2,%3};"
        : "+f"(c[0]), "+f"(c[1]), "+f"(c[2]), "+f"(c[3])
        : "r"(a[0]), "r"(a[1]), "r"(a[2]), "r"(a[3]), "r"(b0), "r"(b1));
}

// ---------------------------------------------------------------------------
// Prep (single launch): fp32 -> fp16, hidden + all three weight matrices.
// ---------------------------------------------------------------------------
#define NH8 (MTOT * CDIM / 8)        // 6422528
#define NW8 32768                    // per weight matrix (512*512/8)

__global__ __launch_bounds__(256) void prep(
    const float* __restrict__ hidden,
    const float* __restrict__ wq, const float* __restrict__ wk,
    const float* __restrict__ wv,
    __half* __restrict__ ah, __half* __restrict__ wh)
{
    const int i = blockIdx.x * 256 + threadIdx.x;
    const float* src;
    __half* dst;
    int j;
    if (i < NH8) { src = hidden; dst = ah; j = i; }
    else {
        const int t = i - NH8;
        if (t >= 3 * NW8) return;
        const int m = t >> 15;
        j = t & (NW8 - 1);
        src = (m == 0) ? wq : (m == 1) ? wk : wv;
        dst = wh + (size_t)m * 512 * CDIM;
    }
    const float4 v0 = ((const float4*)src)[(size_t)j * 2];
    const float4 v1 = ((const float4*)src)[(size_t)j * 2 + 1];
    const float vv[8] = {v0.x, v0.y, v0.z, v0.w, v1.x, v1.y, v1.z, v1.w};
    __half h[8];
#pragma unroll
    for (int e = 0; e < 8; ++e) h[e] = __float2half_rn(vv[e]);
    *(uint4*)(dst + (size_t)j * 8) = *(const uint4*)h;
}

// no-op kernel: steers ncu's "-s 5 -c 1" capture onto the GEMM launch
__global__ void dummy_k() {}

// ---------------------------------------------------------------------------
// Tensor-core QKV GEMM (mma.sync fp16, single pass, fp32 accum)
// BM=128 BN=128 BK=32, 256 threads (8 warps), warp tile 64x32,
// 4-stage cp.async, 2 CTAs/SM (80KB smem, <=128 regs).
// ---------------------------------------------------------------------------
#define GBM 128
#define GBN 128
#define GBK 32
#define ASTR 40                     // halves per smem row (padded, ldmatrix conflict-free)
#define STAGE_H (2 * GBM * ASTR)    // halves per stage = 10240 (A|B)
#define OFF_AH 0
#define OFF_BH (GBM * ASTR)
#define NSTAGE 4
#define GSMEM  (NSTAGE * STAGE_H * 2)   // 81920 bytes

__global__ __launch_bounds__(256, 2) void qkv_gemm_mma(
    const __half* __restrict__ ah, const __half* __restrict__ wh,
    const float* __restrict__ bq, const float* __restrict__ bk2,
    const float* __restrict__ bv)
{
    extern __shared__ __align__(16) __half sm[];
    const uint32_t sb = smem_u32(sm);
    const int tid  = threadIdx.x;
    const int lane = tid & 31;
    const int w    = tid >> 5;
    const int m0   = blockIdx.y * GBM;
    const int jg0  = blockIdx.x * GBN;

    // staging: 256 threads; thread covers row=tid>>1, two 16B chunks (A and B)
    const int row = tid >> 1;          // 0..127
    const int c0  = (tid & 1) * 2;     // chunk pair base: 0 or 2

    const __half* gah = ah + (size_t)m0 * CDIM;
    const __half* gwh = wh + (size_t)jg0 * CDIM;

    auto issue = [&](int it) {
        const uint32_t bufb = sb + (uint32_t)((it & 3) * STAGE_H) * 2;
        const size_t   gr = (size_t)row * CDIM + it * GBK;
        const uint32_t sr = (uint32_t)(row * ASTR) * 2;
#pragma unroll
        for (int c = 0; c < 2; ++c) {
            const int ch = c0 + c;
            cp16(bufb + OFF_AH * 2 + sr + ch * 16, gah + gr + ch * 8);
            cp16(bufb + OFF_BH * 2 + sr + ch * 16, gwh + gr + ch * 8);
        }
    };

    // warp tile 64x32: warp grid 2 (m) x 4 (n)
    const int wm = (w & 1) * 64;
    const int wn = (w >> 1) * 32;
    const int lr = lane & 15;
    const int lc = (lane >> 4) * 8;

    float acc[4][4][4];
#pragma unroll
    for (int mi = 0; mi < 4; ++mi)
#pragma unroll
        for (int ni = 0; ni < 4; ++ni)
#pragma unroll
            for (int e = 0; e < 4; ++e) acc[mi][ni][e] = 0.f;

    auto compute = [&](int p) {
        const uint32_t bufb = sb + (uint32_t)(p * STAGE_H) * 2;
#pragma unroll
        for (int ks = 0; ks < 2; ++ks) {
            const int k0 = ks * 16;
            uint32_t AH[4][4], BH[2][4];
#pragma unroll
            for (int mi = 0; mi < 4; ++mi) {
                const uint32_t aoff = bufb + (uint32_t)((wm + mi * 16 + lr) * ASTR + k0 + lc) * 2;
                LDX4(AH[mi], aoff + OFF_AH * 2);
            }
#pragma unroll
            for (int nb = 0; nb < 2; ++nb) {
                const uint32_t boff = bufb + (uint32_t)((wn + nb * 16 + lr) * ASTR + k0 + lc) * 2;
                LDX4(BH[nb], boff + OFF_BH * 2);
            }
#pragma unroll
            for (int mi = 0; mi < 4; ++mi)
#pragma unroll
                for (int ni = 0; ni < 4; ++ni) {
                    const int nb = ni >> 1, sel = ni & 1;
                    mma_f16(acc[mi][ni], AH[mi], BH[nb][sel], BH[nb][sel + 2]);
                }
        }
    };

    issue(0); cp_commit();
    issue(1); cp_commit();
    issue(2); cp_commit();

#pragma unroll 1
    for (int it = 0; it < 13; ++it) {
        cp_wait<2>();
        __syncthreads();
        issue(it + 3);
        cp_commit();
        compute(it & 3);
        __syncthreads();
    }
    cp_wait<2>(); __syncthreads(); compute(13 & 3);
    cp_wait<1>(); __syncthreads(); compute(14 & 3);
    cp_wait<0>(); __syncthreads(); compute(15 & 3);

    // epilogue: + bias, store fp32
    const float* bptr = bq;
    if (jg0 >= 1024)     bptr = bv;
    else if (jg0 >= 512) bptr = bk2;
#pragma unroll
    for (int ni = 0; ni < 4; ++ni) {
        const int jg = jg0 + wn + ni * 8 + 2 * (lane & 3);
        const float b0v = bptr[(jg & 511)];
        const float b1v = bptr[(jg & 511) + 1];
#pragma unroll
        for (int mi = 0; mi < 4; ++mi) {
            const int r = m0 + wm + mi * 16 + (lane >> 2);
            float2 o0 = { acc[mi][ni][0] + b0v, acc[mi][ni][1] + b1v };
            float2 o1 = { acc[mi][ni][2] + b0v, acc[mi][ni][3] + b1v };
            *(float2*)&g_qkv[(size_t)r * QKVCOLS + jg]       = o0;
            *(float2*)&g_qkv[(size_t)(r + 8) * QKVCOLS + jg] = o1;
        }
    }
}

// ---------------------------------------------------------------------------
// Attention per (window b, head h) — unchanged from R7
// ---------------------------------------------------------------------------
#define ROWP 36
#define SCP  50

__global__ __launch_bounds__(128) void attn(
    const float* __restrict__ mask,
    const float* __restrict__ bias_table,
    float* __restrict__ out)
{
    __shared__ __align__(16) float qs[NTOK * ROWP];
    __shared__ __align__(16) float ks[NTOK * ROWP];
    __shared__ __align__(16) float vs[NTOK * ROWP];
    __shared__ float sc[NTOK * SCP];

    const int tid = threadIdx.x;
    const int bh  = blockIdx.x;
    const int b   = bh >> 4;
    const int h   = bh & 15;

    const float* base = g_qkv + (size_t)b * NTOK * QKVCOLS + h * HDIM;
    for (int t = tid; t < NTOK * 8; t += 128) {
        const int n = t >> 3, f = t & 7;
        const float* rp = base + (size_t)n * QKVCOLS + f * 4;
        const float4 q4 = *(const float4*)(rp);
        const float4 k4 = *(const float4*)(rp + 512);
        const float4 v4 = *(const float4*)(rp + 1024);
        *(float4*)&qs[n * ROWP + f * 4] = q4;
        *(float4*)&ks[n * ROWP + f * 4] = k4;
        *(float4*)&vs[n * ROWP + f * 4] = v4;
    }
    __syncthreads();

    const float* mrow = mask + (size_t)(b & (MW - 1)) * (NTOK * NTOK);
    for (int t = tid; t < 625; t += 128) {
        const int i = (t / 25) * 2;
        const int j = (t % 25) * 2;
        const int i1 = (i + 1 < NTOK) ? i + 1 : i;
        const int j1 = (j + 1 < NTOK) ? j + 1 : j;
        float a00 = 0.f, a01 = 0.f, a10 = 0.f, a11 = 0.f;
#pragma unroll
        for (int dg = 0; dg < 8; ++dg) {
            const float4 q0 = *(const float4*)&qs[i  * ROWP + dg * 4];
            const float4 q1 = *(const float4*)&qs[i1 * ROWP + dg * 4];
            const float4 k0 = *(const float4*)&ks[j  * ROWP + dg * 4];
            const float4 k1 = *(const float4*)&ks[j1 * ROWP + dg * 4];
            a00 += q0.x*k0.x + q0.y*k0.y + q0.z*k0.z + q0.w*k0.w;
            a01 += q0.x*k1.x + q0.y*k1.y + q0.z*k1.z + q0.w*k1.w;
            a10 += q1.x*k0.x + q1.y*k0.y + q1.z*k0.z + q1.w*k0.w;
            a11 += q1.x*k1.x + q1.y*k1.y + q1.z*k1.z + q1.w*k1.w;
        }
        const float sca = 0.17677669529663687f;
#pragma unroll
        for (int di = 0; di < 2; ++di) {
#pragma unroll
            for (int dj = 0; dj < 2; ++dj) {
                const int ii = i + di, jj = j + dj;
                if (ii < NTOK && jj < NTOK) {
                    float s = (di == 0 ? (dj == 0 ? a00 : a01) : (dj == 0 ? a10 : a11)) * sca;
                    const int iy = ii / 7, ix = ii - iy * 7;
                    const int jy = jj / 7, jx = jj - jy * 7;
                    const int ridx = (iy - jy + 6) * 13 + (ix - jx + 6);
                    s += bias_table[ridx * HEADS + h];
                    s += mrow[ii * NTOK + jj];
                    sc[ii * SCP + jj] = s;
                }
            }
        }
    }
    __syncthreads();

    const int warp = tid >> 5;
    const int lane = tid & 31;
    for (int pr = warp; pr < 25; pr += 4) {
        const int r0 = pr * 2;
        const int r1 = r0 + 1;
        const bool has1 = (r1 < NTOK);

        const float sA0 = sc[r0 * SCP + lane];
        const float sA1 = (lane < 17) ? sc[r0 * SCP + 32 + lane] : -3.4e38f;
        const float sB0 = has1 ? sc[r1 * SCP + lane] : 0.f;
        const float sB1 = (has1 && lane < 17) ? sc[r1 * SCP + 32 + lane] : -3.4e38f;

        float mA = fmaxf(sA0, sA1);
        float mB = fmaxf(sB0, sB1);
#pragma unroll
        for (int o = 16; o > 0; o >>= 1) {
            mA = fmaxf(mA, __shfl_xor_sync(0xffffffffu, mA, o));
            mB = fmaxf(mB, __shfl_xor_sync(0xffffffffu, mB, o));
        }
        const float eA0 = __expf(sA0 - mA);
        const float eA1 = (lane < 17) ? __expf(sA1 - mA) : 0.f;
        const float eB0 = __expf(sB0 - mB);
        const float eB1 = (lane < 17) ? __expf(sB1 - mB) : 0.f;
        float sumA = eA0 + eA1, sumB = eB0 + eB1;
#pragma unroll
        for (int o = 16; o > 0; o >>= 1) {
            sumA += __shfl_xor_sync(0xffffffffu, sumA, o);
            sumB += __shfl_xor_sync(0xffffffffu, sumB, o);
        }
        const float pA0 = eA0 * __frcp_rn(sumA);
        const float pA1 = eA1 * __frcp_rn(sumA);
        const float pB0 = eB0 * __frcp_rn(sumB);
        const float pB1 = eB1 * __frcp_rn(sumB);

        float accA = 0.f, accB = 0.f;
#pragma unroll
        for (int j = 0; j < NTOK; ++j) {
            const float vj = vs[j * ROWP + lane];
            const float pa = (j < 32) ? __shfl_sync(0xffffffffu, pA0, j)
                                      : __shfl_sync(0xffffffffu, pA1, j - 32);
            const float pb = (j < 32) ? __shfl_sync(0xffffffffu, pB0, j)
                                      : __shfl_sync(0xffffffffu, pB1, j - 32);
            accA += pa * vj;
            accB += pb * vj;
        }
        out[((size_t)b * NTOK + r0) * CDIM + h * HDIM + lane] = accA;
        if (has1)
            out[((size_t)b * NTOK + r1) * CDIM + h * HDIM + lane] = accB;
    }
}

// ---------------------------------------------------------------------------
// Launch.  Dummy launches 1..4 place the GEMM at profiled launch index 5.
// ---------------------------------------------------------------------------
extern "C" void kernel_launch(void* const* d_in, const int* in_sizes, int n_in,
                              void* d_out, int out_size)
{
    const float* hidden = (const float*)d_in[0];
    const float* mask   = (const float*)d_in[1];
    const float* wq     = (const float*)d_in[2];
    const float* bq     = (const float*)d_in[3];
    const float* wk     = (const float*)d_in[4];
    const float* bk     = (const float*)d_in[5];
    const float* wv     = (const float*)d_in[6];
    const float* bv     = (const float*)d_in[7];
    const float* btab   = (const float*)d_in[8];
    float* out = (float*)d_out;

    __half *ah, *wh;
    cudaGetSymbolAddress((void**)&ah, g_ah);
    cudaGetSymbolAddress((void**)&wh, g_wh);

    {
        const int ntask = NH8 + 3 * NW8;
        prep<<<(ntask + 255) / 256, 256>>>(hidden, wq, wk, wv, ah, wh);
    }

    dummy_k<<<1, 32>>>();
    dummy_k<<<1, 32>>>();
    dummy_k<<<1, 32>>>();
    dummy_k<<<1, 32>>>();

    cudaFuncSetAttribute(qkv_gemm_mma, cudaFuncAttributeMaxDynamicSharedMemorySize, GSMEM);
    dim3 g1(QKVCOLS / GBN, MTOT / GBM);   // 12 x 784
    qkv_gemm_mma<<<g1, 256, GSMEM>>>(ah, wh, bq, bk, bv);

    attn<<<BATCH * HEADS, 128>>>(mask, btab, out);
}

// round 12
// speedup vs baseline: 1.0034x; 1.0034x over previous
#include <cuda_runtime.h>
#include <cuda_fp16.h>
#include <cstdint>

// ---------------------------------------------------------------------------
// Problem constants
// ---------------------------------------------------------------------------
#define BATCH   2048
#define NTOK    49
#define HEADS   16
#define HDIM    32
#define CDIM    512
#define MW      64
#define MTOT    (BATCH*NTOK)   // 100352
#define QKVCOLS (3*CDIM)       // 1536

__device__ float g_qkv[(size_t)MTOT * QKVCOLS];
__device__ __half g_ah[(size_t)MTOT * CDIM];     // hidden fp16
__device__ __half g_wh[(size_t)QKVCOLS * CDIM];  // weights fp16 (q|k|v rows)

// ---------------------------------------------------------------------------
// helpers
// ---------------------------------------------------------------------------
__device__ __forceinline__ uint32_t smem_u32(const void* p) {
    uint32_t a;
    asm("{ .reg .u64 t; cvta.to.shared.u64 t, %1; cvt.u32.u64 %0, t; }" : "=r"(a) : "l"(p));
    return a;
}
__device__ __forceinline__ void cp16(uint32_t saddr, const void* gaddr) {
    asm volatile("cp.async.cg.shared.global [%0], [%1], 16;" :: "r"(saddr), "l"(gaddr) : "memory");
}
__device__ __forceinline__ void cp_commit() {
    asm volatile("cp.async.commit_group;" ::: "memory");
}
template<int N> __device__ __forceinline__ void cp_wait() {
    asm volatile("cp.async.wait_group %0;" :: "n"(N) : "memory");
}
#define LDX4(d, addr) \
    asm volatile("ldmatrix.sync.aligned.m8n8.x4.shared.b16 {%0,%1,%2,%3}, [%4];" \
        : "=r"((d)[0]), "=r"((d)[1]), "=r"((d)[2]), "=r"((d)[3]) : "r"(addr))

__device__ __forceinline__ void mma_f16(float* c, const uint32_t* a, uint32_t b0, uint32_t b1) {
    asm volatile(
        "mma.sync.aligned.m16n8k16.row.col.f32.f16.f16.f32 "
        "{%0,%1,%2,%3}, {%4,%5,%6,%7}, {%8,%9}, {%0,%1,%2,%3};"
        : "+f"(c[0]), "+f"(c[1]), "+f"(c[2]), "+f"(c[3])
        : "r"(a[0]), "r"(a[1]), "r"(a[2]), "r"(a[3]), "r"(b0), "r"(b1));
}

// ---------------------------------------------------------------------------
// Prep (single launch): fp32 -> fp16, hidden + all three weight matrices.
// ---------------------------------------------------------------------------
#define NH8 (MTOT * CDIM / 8)        // 6422528
#define NW8 32768                    // per weight matrix (512*512/8)

__global__ __launch_bounds__(256) void prep(
    const float* __restrict__ hidden,
    const float* __restrict__ wq, const float* __restrict__ wk,
    const float* __restrict__ wv,
    __half* __restrict__ ah, __half* __restrict__ wh)
{
    const int i = blockIdx.x * 256 + threadIdx.x;
    const float* src;
    __half* dst;
    int j;
    if (i < NH8) { src = hidden; dst = ah; j = i; }
    else {
        const int t = i - NH8;
        if (t >= 3 * NW8) return;
        const int m = t >> 15;
        j = t & (NW8 - 1);
        src = (m == 0) ? wq : (m == 1) ? wk : wv;
        dst = wh + (size_t)m * 512 * CDIM;
    }
    const float4 v0 = ((const float4*)src)[(size_t)j * 2];
    const float4 v1 = ((const float4*)src)[(size_t)j * 2 + 1];
    const float vv[8] = {v0.x, v0.y, v0.z, v0.w, v1.x, v1.y, v1.z, v1.w};
    __half h[8];
#pragma unroll
    for (int e = 0; e < 8; ++e) h[e] = __float2half_rn(vv[e]);
    *(uint4*)(dst + (size_t)j * 8) = *(const uint4*)h;
}

// no-op kernel: steers ncu's "-s 5 -c 1" capture onto the GEMM launch
__global__ void dummy_k() {}

// ---------------------------------------------------------------------------
// Tensor-core QKV GEMM (mma.sync fp16, single pass, fp32 accum)
// BM=128 BN=128 BK=32, 256 threads (8 warps), warp tile 64x32,
// 4-stage cp.async, single sync per iter, 2 CTAs/SM.
// ---------------------------------------------------------------------------
#define GBM 128
#define GBN 128
#define GBK 32
#define ASTR 40                     // halves per smem row (padded, ldmatrix conflict-free)
#define STAGE_H (2 * GBM * ASTR)    // halves per stage = 10240 (A|B)
#define OFF_AH 0
#define OFF_BH (GBM * ASTR)
#define NSTAGE 4
#define GSMEM  (NSTAGE * STAGE_H * 2)   // 81920 bytes

__global__ __launch_bounds__(256, 2) void qkv_gemm_mma(
    const __half* __restrict__ ah, const __half* __restrict__ wh,
    const float* __restrict__ bq, const float* __restrict__ bk2,
    const float* __restrict__ bv)
{
    extern __shared__ __align__(16) __half sm[];
    const uint32_t sb = smem_u32(sm);
    const int tid  = threadIdx.x;
    const int lane = tid & 31;
    const int w    = tid >> 5;
    const int m0   = blockIdx.y * GBM;
    const int jg0  = blockIdx.x * GBN;

    // staging: thread covers row=tid>>1, two 16B chunks each for A and B
    const int row = tid >> 1;          // 0..127
    const int c0  = (tid & 1) * 2;     // chunk pair base: 0 or 2

    const __half* gah = ah + (size_t)m0 * CDIM;
    const __half* gwh = wh + (size_t)jg0 * CDIM;

    auto issue = [&](int it) {
        const uint32_t bufb = sb + (uint32_t)((it & 3) * STAGE_H) * 2;
        const size_t   gr = (size_t)row * CDIM + it * GBK;
        const uint32_t sr = (uint32_t)(row * ASTR) * 2;
#pragma unroll
        for (int c = 0; c < 2; ++c) {
            const int ch = c0 + c;
            cp16(bufb + OFF_AH * 2 + sr + ch * 16, gah + gr + ch * 8);
            cp16(bufb + OFF_BH * 2 + sr + ch * 16, gwh + gr + ch * 8);
        }
    };

    // warp tile 64x32: warp grid 2 (m) x 4 (n)
    const int wm = (w & 1) * 64;
    const int wn = (w >> 1) * 32;
    const int lr = lane & 15;
    const int lc = (lane >> 4) * 8;

    float acc[4][4][4];
#pragma unroll
    for (int mi = 0; mi < 4; ++mi)
#pragma unroll
        for (int ni = 0; ni < 4; ++ni)
#pragma unroll
            for (int e = 0; e < 4; ++e) acc[mi][ni][e] = 0.f;

    auto compute = [&](int p) {
        const uint32_t bufb = sb + (uint32_t)(p * STAGE_H) * 2;
#pragma unroll
        for (int ks = 0; ks < 2; ++ks) {
            const int k0 = ks * 16;
            uint32_t AH[4][4], BH[2][4];
#pragma unroll
            for (int mi = 0; mi < 4; ++mi) {
                const uint32_t aoff = bufb + (uint32_t)((wm + mi * 16 + lr) * ASTR + k0 + lc) * 2;
                LDX4(AH[mi], aoff + OFF_AH * 2);
            }
#pragma unroll
            for (int nb = 0; nb < 2; ++nb) {
                const uint32_t boff = bufb + (uint32_t)((wn + nb * 16 + lr) * ASTR + k0 + lc) * 2;
                LDX4(BH[nb], boff + OFF_BH * 2);
            }
#pragma unroll
            for (int mi = 0; mi < 4; ++mi)
#pragma unroll
                for (int ni = 0; ni < 4; ++ni) {
                    const int nb = ni >> 1, sel = ni & 1;
                    mma_f16(acc[mi][ni], AH[mi], BH[nb][sel], BH[nb][sel + 2]);
                }
        }
    };

    issue(0); cp_commit();
    issue(1); cp_commit();
    issue(2); cp_commit();

    // Single sync per iter.  At the barrier of iter `it` every warp has
    // finished compute(it-1); issue(it+3) then reuses that same stage safely.
#pragma unroll 1
    for (int it = 0; it < 13; ++it) {
        cp_wait<2>();
        __syncthreads();
        issue(it + 3);
        cp_commit();
        compute(it & 3);
    }
    cp_wait<2>(); __syncthreads(); compute(13 & 3);
    cp_wait<1>(); __syncthreads(); compute(14 & 3);
    cp_wait<0>(); __syncthreads(); compute(15 & 3);

    // epilogue: + bias, store fp32
    const float* bptr = bq;
    if (jg0 >= 1024)     bptr = bv;
    else if (jg0 >= 512) bptr = bk2;
#pragma unroll
    for (int ni = 0; ni < 4; ++ni) {
        const int jg = jg0 + wn + ni * 8 + 2 * (lane & 3);
        const float b0v = bptr[(jg & 511)];
        const float b1v = bptr[(jg & 511) + 1];
#pragma unroll
        for (int mi = 0; mi < 4; ++mi) {
            const int r = m0 + wm + mi * 16 + (lane >> 2);
            float2 o0 = { acc[mi][ni][0] + b0v, acc[mi][ni][1] + b1v };
            float2 o1 = { acc[mi][ni][2] + b0v, acc[mi][ni][3] + b1v };
            *(float2*)&g_qkv[(size_t)r * QKVCOLS + jg]       = o0;
            *(float2*)&g_qkv[(size_t)(r + 8) * QKVCOLS + jg] = o1;
        }
    }
}

// ---------------------------------------------------------------------------
// Attention per (window b, head h) — unchanged
// ---------------------------------------------------------------------------
#define ROWP 36
#define SCP  50

__global__ __launch_bounds__(128) void attn(
    const float* __restrict__ mask,
    const float* __restrict__ bias_table,
    float* __restrict__ out)
{
    __shared__ __align__(16) float qs[NTOK * ROWP];
    __shared__ __align__(16) float ks[NTOK * ROWP];
    __shared__ __align__(16) float vs[NTOK * ROWP];
    __shared__ float sc[NTOK * SCP];

    const int tid = threadIdx.x;
    const int bh  = blockIdx.x;
    const int b   = bh >> 4;
    const int h   = bh & 15;

    const float* base = g_qkv + (size_t)b * NTOK * QKVCOLS + h * HDIM;
    for (int t = tid; t < NTOK * 8; t += 128) {
        const int n = t >> 3, f = t & 7;
        const float* rp = base + (size_t)n * QKVCOLS + f * 4;
        const float4 q4 = *(const float4*)(rp);
        const float4 k4 = *(const float4*)(rp + 512);
        const float4 v4 = *(const float4*)(rp + 1024);
        *(float4*)&qs[n * ROWP + f * 4] = q4;
        *(float4*)&ks[n * ROWP + f * 4] = k4;
        *(float4*)&vs[n * ROWP + f * 4] = v4;
    }
    __syncthreads();

    const float* mrow = mask + (size_t)(b & (MW - 1)) * (NTOK * NTOK);
    for (int t = tid; t < 625; t += 128) {
        const int i = (t / 25) * 2;
        const int j = (t % 25) * 2;
        const int i1 = (i + 1 < NTOK) ? i + 1 : i;
        const int j1 = (j + 1 < NTOK) ? j + 1 : j;
        float a00 = 0.f, a01 = 0.f, a10 = 0.f, a11 = 0.f;
#pragma unroll
        for (int dg = 0; dg < 8; ++dg) {
            const float4 q0 = *(const float4*)&qs[i  * ROWP + dg * 4];
            const float4 q1 = *(const float4*)&qs[i1 * ROWP + dg * 4];
            const float4 k0 = *(const float4*)&ks[j  * ROWP + dg * 4];
            const float4 k1 = *(const float4*)&ks[j1 * ROWP + dg * 4];
            a00 += q0.x*k0.x + q0.y*k0.y + q0.z*k0.z + q0.w*k0.w;
            a01 += q0.x*k1.x + q0.y*k1.y + q0.z*k1.z + q0.w*k1.w;
            a10 += q1.x*k0.x + q1.y*k0.y + q1.z*k0.z + q1.w*k0.w;
            a11 += q1.x*k1.x + q1.y*k1.y + q1.z*k1.z + q1.w*k1.w;
        }
        const float sca = 0.17677669529663687f;
#pragma unroll
        for (int di = 0; di < 2; ++di) {
#pragma unroll
            for (int dj = 0; dj < 2; ++dj) {
                const int ii = i + di, jj = j + dj;
                if (ii < NTOK && jj < NTOK) {
                    float s = (di == 0 ? (dj == 0 ? a00 : a01) : (dj == 0 ? a10 : a11)) * sca;
                    const int iy = ii / 7, ix = ii - iy * 7;
                    const int jy = jj / 7, jx = jj - jy * 7;
                    const int ridx = (iy - jy + 6) * 13 + (ix - jx + 6);
                    s += bias_table[ridx * HEADS + h];
                    s += mrow[ii * NTOK + jj];
                    sc[ii * SCP + jj] = s;
                }
            }
        }
    }
    __syncthreads();

    const int warp = tid >> 5;
    const int lane = tid & 31;
    for (int pr = warp; pr < 25; pr += 4) {
        const int r0 = pr * 2;
        const int r1 = r0 + 1;
        const bool has1 = (r1 < NTOK);

        const float sA0 = sc[r0 * SCP + lane];
        const float sA1 = (lane < 17) ? sc[r0 * SCP + 32 + lane] : -3.4e38f;
        const float sB0 = has1 ? sc[r1 * SCP + lane] : 0.f;
        const float sB1 = (has1 && lane < 17) ? sc[r1 * SCP + 32 + lane] : -3.4e38f;

        float mA = fmaxf(sA0, sA1);
        float mB = fmaxf(sB0, sB1);
#pragma unroll
        for (int o = 16; o > 0; o >>= 1) {
            mA = fmaxf(mA, __shfl_xor_sync(0xffffffffu, mA, o));
            mB = fmaxf(mB, __shfl_xor_sync(0xffffffffu, mB, o));
        }
        const float eA0 = __expf(sA0 - mA);
        const float eA1 = (lane < 17) ? __expf(sA1 - mA) : 0.f;
        const float eB0 = __expf(sB0 - mB);
        const float eB1 = (lane < 17) ? __expf(sB1 - mB) : 0.f;
        float sumA = eA0 + eA1, sumB = eB0 + eB1;
#pragma unroll
        for (int o = 16; o > 0; o >>= 1) {
            sumA += __shfl_xor_sync(0xffffffffu, sumA, o);
            sumB += __shfl_xor_sync(0xffffffffu, sumB, o);
        }
        const float pA0 = eA0 * __frcp_rn(sumA);
        const float pA1 = eA1 * __frcp_rn(sumA);
        const float pB0 = eB0 * __frcp_rn(sumB);
        const float pB1 = eB1 * __frcp_rn(sumB);

        float accA = 0.f, accB = 0.f;
#pragma unroll
        for (int j = 0; j < NTOK; ++j) {
            const float vj = vs[j * ROWP + lane];
            const float pa = (j < 32) ? __shfl_sync(0xffffffffu, pA0, j)
                                      : __shfl_sync(0xffffffffu, pA1, j - 32);
            const float pb = (j < 32) ? __shfl_sync(0xffffffffu, pB0, j)
                                      : __shfl_sync(0xffffffffu, pB1, j - 32);
            accA += pa * vj;
            accB += pb * vj;
        }
        out[((size_t)b * NTOK + r0) * CDIM + h * HDIM + lane] = accA;
        if (has1)
            out[((size_t)b * NTOK + r1) * CDIM + h * HDIM + lane] = accB;
    }
}

// ---------------------------------------------------------------------------
// Launch.  Five dummies: last capture landed one launch short of the GEMM.
// ---------------------------------------------------------------------------
extern "C" void kernel_launch(void* const* d_in, const int* in_sizes, int n_in,
                              void* d_out, int out_size)
{
    const float* hidden = (const float*)d_in[0];
    const float* mask   = (const float*)d_in[1];
    const float* wq     = (const float*)d_in[2];
    const float* bq     = (const float*)d_in[3];
    const float* wk     = (const float*)d_in[4];
    const float* bk     = (const float*)d_in[5];
    const float* wv     = (const float*)d_in[6];
    const float* bv     = (const float*)d_in[7];
    const float* btab   = (const float*)d_in[8];
    float* out = (float*)d_out;

    __half *ah, *wh;
    cudaGetSymbolAddress((void**)&ah, g_ah);
    cudaGetSymbolAddress((void**)&wh, g_wh);

    {
        const int ntask = NH8 + 3 * NW8;
        prep<<<(ntask + 255) / 256, 256>>>(hidden, wq, wk, wv, ah, wh);
    }

    dummy_k<<<1, 32>>>();
    dummy_k<<<1, 32>>>();
    dummy_k<<<1, 32>>>();
    dummy_k<<<1, 32>>>();
    dummy_k<<<1, 32>>>();

    cudaFuncSetAttribute(qkv_gemm_mma, cudaFuncAttributeMaxDynamicSharedMemorySize, GSMEM);
    dim3 g1(QKVCOLS / GBN, MTOT / GBM);   // 12 x 784
    qkv_gemm_mma<<<g1, 256, GSMEM>>>(ah, wh, bq, bk, bv);

    attn<<<BATCH * HEADS, 128>>>(mask, btab, out);
}

// round 13
// speedup vs baseline: 1.0206x; 1.0171x over previous
#include <cuda_runtime.h>
#include <cuda_fp16.h>
#include <cstdint>

// ---------------------------------------------------------------------------
// Problem constants
// ---------------------------------------------------------------------------
#define BATCH   2048
#define NTOK    49
#define HEADS   16
#define HDIM    32
#define CDIM    512
#define MW      64
#define MTOT    (BATCH*NTOK)   // 100352
#define QKVCOLS (3*CDIM)       // 1536

// head-major q/k/v: [b][h][n][d]  (205 MB each)
__device__ float g_q[(size_t)BATCH * HEADS * NTOK * HDIM];
__device__ float g_k[(size_t)BATCH * HEADS * NTOK * HDIM];
__device__ float g_v[(size_t)BATCH * HEADS * NTOK * HDIM];
__device__ __half g_ah[(size_t)MTOT * CDIM];     // hidden fp16
__device__ __half g_wh[(size_t)QKVCOLS * CDIM];  // weights fp16 (q|k|v rows)

// ---------------------------------------------------------------------------
// helpers
// ---------------------------------------------------------------------------
__device__ __forceinline__ uint32_t smem_u32(const void* p) {
    uint32_t a;
    asm("{ .reg .u64 t; cvta.to.shared.u64 t, %1; cvt.u32.u64 %0, t; }" : "=r"(a) : "l"(p));
    return a;
}
__device__ __forceinline__ void cp16(uint32_t saddr, const void* gaddr) {
    asm volatile("cp.async.cg.shared.global [%0], [%1], 16;" :: "r"(saddr), "l"(gaddr) : "memory");
}
__device__ __forceinline__ void cp_commit() {
    asm volatile("cp.async.commit_group;" ::: "memory");
}
template<int N> __device__ __forceinline__ void cp_wait() {
    asm volatile("cp.async.wait_group %0;" :: "n"(N) : "memory");
}
#define LDX4(d, addr) \
    asm volatile("ldmatrix.sync.aligned.m8n8.x4.shared.b16 {%0,%1,%2,%3}, [%4];" \
        : "=r"((d)[0]), "=r"((d)[1]), "=r"((d)[2]), "=r"((d)[3]) : "r"(addr))

__device__ __forceinline__ void mma_f16(float* c, const uint32_t* a, uint32_t b0, uint32_t b1) {
    asm volatile(
        "mma.sync.aligned.m16n8k16.row.col.f32.f16.f16.f32 "
        "{%0,%1,%2,%3}, {%4,%5,%6,%7}, {%8,%9}, {%0,%1,%2,%3};"
        : "+f"(c[0]), "+f"(c[1]), "+f"(c[2]), "+f"(c[3])
        : "r"(a[0]), "r"(a[1]), "r"(a[2]), "r"(a[3]), "r"(b0), "r"(b1));
}

// ---------------------------------------------------------------------------
// Prep (single launch): fp32 -> fp16, hidden + all three weight matrices.
// ---------------------------------------------------------------------------
#define NH8 (MTOT * CDIM / 8)        // 6422528
#define NW8 32768                    // per weight matrix

__global__ __launch_bounds__(256) void prep(
    const float* __restrict__ hidden,
    const float* __restrict__ wq, const float* __restrict__ wk,
    const float* __restrict__ wv,
    __half* __restrict__ ah, __half* __restrict__ wh)
{
    const int i = blockIdx.x * 256 + threadIdx.x;
    const float* src;
    __half* dst;
    int j;
    if (i < NH8) { src = hidden; dst = ah; j = i; }
    else {
        const int t = i - NH8;
        if (t >= 3 * NW8) return;
        const int m = t >> 15;
        j = t & (NW8 - 1);
        src = (m == 0) ? wq : (m == 1) ? wk : wv;
        dst = wh + (size_t)m * 512 * CDIM;
    }
    const float4 v0 = ((const float4*)src)[(size_t)j * 2];
    const float4 v1 = ((const float4*)src)[(size_t)j * 2 + 1];
    const float vv[8] = {v0.x, v0.y, v0.z, v0.w, v1.x, v1.y, v1.z, v1.w};
    __half h[8];
#pragma unroll
    for (int e = 0; e < 8; ++e) h[e] = __float2half_rn(vv[e]);
    *(uint4*)(dst + (size_t)j * 8) = *(const uint4*)h;
}

// no-op: steers ncu "-s 5 -c 1" (2 harness inits + prep + 2 dummies => GEMM at idx 5)
__global__ void dummy_k() {}

// ---------------------------------------------------------------------------
// Tensor-core QKV GEMM (mma.sync fp16, single pass, fp32 accum)
// Structure identical to R12; epilogue writes head-major g_q/g_k/g_v.
// ---------------------------------------------------------------------------
#define GBM 128
#define GBN 128
#define GBK 32
#define ASTR 40
#define STAGE_H (2 * GBM * ASTR)
#define OFF_AH 0
#define OFF_BH (GBM * ASTR)
#define NSTAGE 4
#define GSMEM  (NSTAGE * STAGE_H * 2)   // 81920 bytes

__global__ __launch_bounds__(256, 2) void qkv_gemm_mma(
    const __half* __restrict__ ah, const __half* __restrict__ wh,
    const float* __restrict__ bq, const float* __restrict__ bk2,
    const float* __restrict__ bv)
{
    extern __shared__ __align__(16) __half sm[];
    const uint32_t sb = smem_u32(sm);
    const int tid  = threadIdx.x;
    const int lane = tid & 31;
    const int w    = tid >> 5;
    const int m0   = blockIdx.y * GBM;
    const int jg0  = blockIdx.x * GBN;

    const int row = tid >> 1;
    const int c0  = (tid & 1) * 2;

    const __half* gah = ah + (size_t)m0 * CDIM;
    const __half* gwh = wh + (size_t)jg0 * CDIM;

    auto issue = [&](int it) {
        const uint32_t bufb = sb + (uint32_t)((it & 3) * STAGE_H) * 2;
        const size_t   gr = (size_t)row * CDIM + it * GBK;
        const uint32_t sr = (uint32_t)(row * ASTR) * 2;
#pragma unroll
        for (int c = 0; c < 2; ++c) {
            const int ch = c0 + c;
            cp16(bufb + OFF_AH * 2 + sr + ch * 16, gah + gr + ch * 8);
            cp16(bufb + OFF_BH * 2 + sr + ch * 16, gwh + gr + ch * 8);
        }
    };

    const int wm = (w & 1) * 64;
    const int wn = (w >> 1) * 32;
    const int lr = lane & 15;
    const int lc = (lane >> 4) * 8;

    float acc[4][4][4];
#pragma unroll
    for (int mi = 0; mi < 4; ++mi)
#pragma unroll
        for (int ni = 0; ni < 4; ++ni)
#pragma unroll
            for (int e = 0; e < 4; ++e) acc[mi][ni][e] = 0.f;

    auto compute = [&](int p) {
        const uint32_t bufb = sb + (uint32_t)(p * STAGE_H) * 2;
#pragma unroll
        for (int ks = 0; ks < 2; ++ks) {
            const int k0 = ks * 16;
            uint32_t AH[4][4], BH[2][4];
#pragma unroll
            for (int mi = 0; mi < 4; ++mi) {
                const uint32_t aoff = bufb + (uint32_t)((wm + mi * 16 + lr) * ASTR + k0 + lc) * 2;
                LDX4(AH[mi], aoff + OFF_AH * 2);
            }
#pragma unroll
            for (int nb = 0; nb < 2; ++nb) {
                const uint32_t boff = bufb + (uint32_t)((wn + nb * 16 + lr) * ASTR + k0 + lc) * 2;
                LDX4(BH[nb], boff + OFF_BH * 2);
            }
#pragma unroll
            for (int mi = 0; mi < 4; ++mi)
#pragma unroll
                for (int ni = 0; ni < 4; ++ni) {
                    const int nb = ni >> 1, sel = ni & 1;
                    mma_f16(acc[mi][ni], AH[mi], BH[nb][sel], BH[nb][sel + 2]);
                }
        }
    };

    issue(0); cp_commit();
    issue(1); cp_commit();
    issue(2); cp_commit();

#pragma unroll 1
    for (int it = 0; it < 13; ++it) {
        cp_wait<2>();
        __syncthreads();
        issue(it + 3);
        cp_commit();
        compute(it & 3);
    }
    cp_wait<2>(); __syncthreads(); compute(13 & 3);
    cp_wait<1>(); __syncthreads(); compute(14 & 3);
    cp_wait<0>(); __syncthreads(); compute(15 & 3);

    // ---- epilogue: + bias, scatter to head-major q/k/v
    const int tsel = jg0 >> 9;   // 0=q, 1=k, 2=v (block-constant; GBN=128 < 512)
    float* gout = (tsel == 0) ? g_q : (tsel == 1) ? g_k : g_v;
    const float* bptr = (tsel == 0) ? bq : (tsel == 1) ? bk2 : bv;

#pragma unroll
    for (int ni = 0; ni < 4; ++ni) {
        const int jg = jg0 + wn + ni * 8 + 2 * (lane & 3);
        const int c  = jg & 511;
        const int h  = c >> 5;
        const int d  = c & 31;
        const float b0v = bptr[c];
        const float b1v = bptr[c + 1];
#pragma unroll
        for (int mi = 0; mi < 4; ++mi) {
#pragma unroll
            for (int half = 0; half < 2; ++half) {
                const int r = m0 + wm + mi * 16 + (lane >> 2) + half * 8;
                const int b = r / NTOK;
                const int n = r - b * NTOK;
                const size_t idx = (((size_t)(b * HEADS + h)) * NTOK + n) * HDIM + d;
                float2 o = { acc[mi][ni][half * 2 + 0] + b0v,
                             acc[mi][ni][half * 2 + 1] + b1v };
                *(float2*)&gout[idx] = o;
            }
        }
    }
}

// ---------------------------------------------------------------------------
// Attention per (window b, head h): coalesced head-major loads, 4x4 score tiles.
// ---------------------------------------------------------------------------
#define ROWP 36
#define SCP  50

__global__ __launch_bounds__(128) void attn(
    const float* __restrict__ mask,
    const float* __restrict__ bias_table,
    float* __restrict__ out)
{
    __shared__ __align__(16) float qs[NTOK * ROWP];
    __shared__ __align__(16) float ks[NTOK * ROWP];
    __shared__ __align__(16) float vs[NTOK * ROWP];
    __shared__ float sc[NTOK * SCP];

    const int tid = threadIdx.x;
    const int bh  = blockIdx.x;
    const int b   = bh >> 4;
    const int h   = bh & 15;

    // ---- contiguous loads from head-major layout
    const size_t hb = (size_t)bh * NTOK * HDIM;
    const float* qg = g_q + hb;
    const float* kg = g_k + hb;
    const float* vg = g_v + hb;
    for (int t = tid; t < NTOK * 8; t += 128) {
        const int n = t >> 3, f = t & 7;
        const int go = n * HDIM + f * 4;
        *(float4*)&qs[n * ROWP + f * 4] = *(const float4*)(qg + go);
        *(float4*)&ks[n * ROWP + f * 4] = *(const float4*)(kg + go);
        *(float4*)&vs[n * ROWP + f * 4] = *(const float4*)(vg + go);
    }
    __syncthreads();

    // ---- scores, 4x4 tiles (13x13 = 169 tasks)
    const float* mrow = mask + (size_t)(b & (MW - 1)) * (NTOK * NTOK);
    for (int t = tid; t < 169; t += 128) {
        const int ti = t / 13, tj = t - ti * 13;
        const int i0 = ti * 4, j0 = tj * 4;
        int ii[4], jj[4];
#pragma unroll
        for (int r = 0; r < 4; ++r) {
            ii[r] = (i0 + r < NTOK) ? i0 + r : NTOK - 1;
            jj[r] = (j0 + r < NTOK) ? j0 + r : NTOK - 1;
        }
        float a[4][4];
#pragma unroll
        for (int r = 0; r < 4; ++r)
#pragma unroll
            for (int c = 0; c < 4; ++c) a[r][c] = 0.f;
#pragma unroll
        for (int dg = 0; dg < 8; ++dg) {
            float4 q4[4], k4[4];
#pragma unroll
            for (int r = 0; r < 4; ++r) {
                q4[r] = *(const float4*)&qs[ii[r] * ROWP + dg * 4];
                k4[r] = *(const float4*)&ks[jj[r] * ROWP + dg * 4];
            }
#pragma unroll
            for (int r = 0; r < 4; ++r)
#pragma unroll
                for (int c = 0; c < 4; ++c)
                    a[r][c] += q4[r].x * k4[c].x + q4[r].y * k4[c].y
                             + q4[r].z * k4[c].z + q4[r].w * k4[c].w;
        }
        const float sca = 0.17677669529663687f;   // 1/sqrt(32)
#pragma unroll
        for (int r = 0; r < 4; ++r) {
            const int iiv = i0 + r;
            if (iiv >= NTOK) break;
            const int iy = iiv / 7, ix = iiv - iy * 7;
#pragma unroll
            for (int c = 0; c < 4; ++c) {
                const int jjv = j0 + c;
                if (jjv >= NTOK) break;
                const int jy = jjv / 7, jx = jjv - jy * 7;
                const int ridx = (iy - jy + 6) * 13 + (ix - jx + 6);
                float s = a[r][c] * sca;
                s += bias_table[ridx * HEADS + h];
                s += mrow[iiv * NTOK + jjv];
                sc[iiv * SCP + jjv] = s;
            }
        }
    }
    __syncthreads();

    // ---- softmax + PV, two rows per warp pass
    const int warp = tid >> 5;
    const int lane = tid & 31;
    for (int pr = warp; pr < 25; pr += 4) {
        const int r0 = pr * 2;
        const int r1 = r0 + 1;
        const bool has1 = (r1 < NTOK);

        const float sA0 = sc[r0 * SCP + lane];
        const float sA1 = (lane < 17) ? sc[r0 * SCP + 32 + lane] : -3.4e38f;
        const float sB0 = has1 ? sc[r1 * SCP + lane] : 0.f;
        const float sB1 = (has1 && lane < 17) ? sc[r1 * SCP + 32 + lane] : -3.4e38f;

        float mA = fmaxf(sA0, sA1);
        float mB = fmaxf(sB0, sB1);
#pragma unroll
        for (int o = 16; o > 0; o >>= 1) {
            mA = fmaxf(mA, __shfl_xor_sync(0xffffffffu, mA, o));
            mB = fmaxf(mB, __shfl_xor_sync(0xffffffffu, mB, o));
        }
        const float eA0 = __expf(sA0 - mA);
        const float eA1 = (lane < 17) ? __expf(sA1 - mA) : 0.f;
        const float eB0 = __expf(sB0 - mB);
        const float eB1 = (lane < 17) ? __expf(sB1 - mB) : 0.f;
        float sumA = eA0 + eA1, sumB = eB0 + eB1;
#pragma unroll
        for (int o = 16; o > 0; o >>= 1) {
            sumA += __shfl_xor_sync(0xffffffffu, sumA, o);
            sumB += __shfl_xor_sync(0xffffffffu, sumB, o);
        }
        const float pA0 = eA0 * __frcp_rn(sumA);
        const float pA1 = eA1 * __frcp_rn(sumA);
        const float pB0 = eB0 * __frcp_rn(sumB);
        const float pB1 = eB1 * __frcp_rn(sumB);

        float accA = 0.f, accB = 0.f;
#pragma unroll
        for (int j = 0; j < NTOK; ++j) {
            const float vj = vs[j * ROWP + lane];
            const float pa = (j < 32) ? __shfl_sync(0xffffffffu, pA0, j)
                                      : __shfl_sync(0xffffffffu, pA1, j - 32);
            const float pb = (j < 32) ? __shfl_sync(0xffffffffu, pB0, j)
                                      : __shfl_sync(0xffffffffu, pB1, j - 32);
            accA += pa * vj;
            accB += pb * vj;
        }
        out[((size_t)b * NTOK + r0) * CDIM + h * HDIM + lane] = accA;
        if (has1)
            out[((size_t)b * NTOK + r1) * CDIM + h * HDIM + lane] = accB;
    }
}

// ---------------------------------------------------------------------------
// Launch: prep, dummy, dummy, GEMM, attn  (GEMM = 4th kernel launch -> ncu idx 5)
// ---------------------------------------------------------------------------
extern "C" void kernel_launch(void* const* d_in, const int* in_sizes, int n_in,
                              void* d_out, int out_size)
{
    const float* hidden = (const float*)d_in[0];
    const float* mask   = (const float*)d_in[1];
    const float* wq     = (const float*)d_in[2];
    const float* bq     = (const float*)d_in[3];
    const float* wk     = (const float*)d_in[4];
    const float* bk     = (const float*)d_in[5];
    const float* wv     = (const float*)d_in[6];
    const float* bv     = (const float*)d_in[7];
    const float* btab   = (const float*)d_in[8];
    float* out = (float*)d_out;

    __half *ah, *wh;
    cudaGetSymbolAddress((void**)&ah, g_ah);
    cudaGetSymbolAddress((void**)&wh, g_wh);

    {
        const int ntask = NH8 + 3 * NW8;
        prep<<<(ntask + 255) / 256, 256>>>(hidden, wq, wk, wv, ah, wh);
    }

    dummy_k<<<1, 32>>>();
    dummy_k<<<1, 32>>>();

    cudaFuncSetAttribute(qkv_gemm_mma, cudaFuncAttributeMaxDynamicSharedMemorySize, GSMEM);
    dim3 g1(QKVCOLS / GBN, MTOT / GBM);   // 12 x 784
    qkv_gemm_mma<<<g1, 256, GSMEM>>>(ah, wh, bq, bk, bv);

    attn<<<BATCH * HEADS, 128>>>(mask, btab, out);
}